// round 3
// baseline (speedup 1.0000x reference)
#include <cuda_runtime.h>
#include <math.h>

// Problem constants
#define cB   64
#define cL   2048
#define cT   1024
#define cD   128
#define cE   512
#define cH   8
#define cP   3
#define NHP  24      // H*P score functions
#define NF   66      // 64 sin features + t + const
#define cLAT 256
#define cHID 512

// ---------------- device scratch (static, no allocation) ----------------
__device__ float g_q[cP * cE];            // q = query@W_q + b_q  (3x512)
__device__ float g_kbar[cE];              // sum_{e%8!=0} w_te[e]*W_k[e,j]
__device__ float g_cbar[cE];              // sum_{e%8!=0} b_te[e]*W_k[e,j] + b_k[j]
__device__ float g_A[NHP * NF];           // score coefficients A[hp][i]
__device__ float g_w[cB * NHP * cL];      // scores, layout [b][hp][l]
__device__ float g_mx[cB * NHP];          // per (b,hp) max
__device__ float g_num[cB * NHP * cD];    // attention numerators
__device__ float g_den[cB * NHP * cD];    // attention denominators
__device__ float g_boeff[cLAT];           // b_o + ones-part of W_o
__device__ float g_coeffs[cB * cP * cLAT];// c0,c1,c2 per b
__device__ float g_gg[cB * 3 * cHID];     // g0(+b1), g1, g2 per b

// ---------------- K0: zero accumulators (graph-replay safe) ----------------
__global__ void k_zero() {
    int i = blockIdx.x * blockDim.x + threadIdx.x;
    if (i < cB * NHP * cD) { g_num[i] = 0.f; g_den[i] = 0.f; }
}

// ---------------- K1a: q[p][j] ----------------
__global__ void k_q(const float* __restrict__ query, const float* __restrict__ Wq,
                    const float* __restrict__ bq) {
    int p = blockIdx.x, j = threadIdx.x;
    __shared__ float qs[cE];
    for (int e = threadIdx.x; e < cE; e += blockDim.x) qs[e] = query[p * cE + e];
    __syncthreads();
    float acc = bq[j];
    for (int e = 0; e < cE; e++) acc = fmaf(qs[e], Wq[e * cE + j], acc);
    g_q[p * cE + j] = acc;
}

// ---------------- K1b: kbar / cbar ----------------
__global__ void k_kbar(const float* __restrict__ wte, const float* __restrict__ bte,
                       const float* __restrict__ Wk, const float* __restrict__ bk) {
    int j = threadIdx.x;
    float ak = 0.f, ac = bk[j];
    for (int e = 0; e < cE; e++) {
        if (e & 7) {  // e % 8 != 0 -> linear (non-sin) feature
            float w = Wk[e * cE + j];
            ak = fmaf(wte[e], w, ak);
            ac = fmaf(bte[e], w, ac);
        }
    }
    g_kbar[j] = ak; g_cbar[j] = ac;
}

// ---------------- K1c: A[hp][i] ----------------
__global__ void k_A(const float* __restrict__ Wk) {
    int hp = blockIdx.x, i = threadIdx.x;
    if (i >= NF) return;
    int h = hp / cP, p = hp % cP;
    const float* qr = &g_q[p * cE + h * 64];
    float acc = 0.f;
    if (i < 64) {
        const float* wr = &Wk[(8 * i) * cE + h * 64];
        for (int j = 0; j < 64; j++) acc = fmaf(qr[j], wr[j], acc);
    } else if (i == 64) {
        const float* wr = &g_kbar[h * 64];
        for (int j = 0; j < 64; j++) acc = fmaf(qr[j], wr[j], acc);
    } else {
        const float* wr = &g_cbar[h * 64];
        for (int j = 0; j < 64; j++) acc = fmaf(qr[j], wr[j], acc);
    }
    g_A[hp * NF + i] = acc * 0.125f;  // / sqrt(ek)=8
}

// ---------------- K1d: b_o_eff (ones-part of x folded into bias) ----------------
__global__ void k_boeff(const float* __restrict__ Wo, const float* __restrict__ bo) {
    int m = threadIdx.x;
    float acc = bo[m];
    for (int h = 0; h < cH; h++)
        for (int c = 128; c < 256; c++)
            acc += Wo[(h * 256 + c) * cLAT + m];
    g_boeff[m] = acc;
}

// ---------------- K2: scores[b][hp][l] = A[hp]·phi(t) ----------------
__global__ void __launch_bounds__(128) k_scores(const float* __restrict__ tsteps,
                                                const float* __restrict__ wte,
                                                const float* __restrict__ bte) {
    __shared__ float As[NHP * NF];
    __shared__ float sw[64], sb[64];
    int tid = threadIdx.x;
    for (int idx = tid; idx < NHP * NF; idx += 128) As[idx] = g_A[idx];
    if (tid < 64) { sw[tid] = wte[8 * tid]; sb[tid] = bte[8 * tid]; }
    __syncthreads();

    int b = blockIdx.y;
    int l = blockIdx.x * 128 + tid;
    float t = tsteps[b * cL + l];
    float phi[64];
#pragma unroll
    for (int i = 0; i < 64; i++) phi[i] = sinf(fmaf(t, sw[i], sb[i]));

    for (int hp = 0; hp < NHP; hp++) {
        const float* Ar = &As[hp * NF];
        float sc = fmaf(Ar[64], t, Ar[65]);
#pragma unroll
        for (int i = 0; i < 64; i++) sc = fmaf(Ar[i], phi[i], sc);
        g_w[(b * NHP + hp) * cL + l] = sc;
    }
}

// ---------------- K3: per (b,hp) max over l ----------------
__global__ void k_max() {
    __shared__ float red[128];
    int base = blockIdx.x * cL;
    float m = -1e30f;
    for (int l = threadIdx.x; l < cL; l += 128) m = fmaxf(m, g_w[base + l]);
    red[threadIdx.x] = m;
    __syncthreads();
    for (int s = 64; s > 0; s >>= 1) {
        if (threadIdx.x < s) red[threadIdx.x] = fmaxf(red[threadIdx.x], red[threadIdx.x + s]);
        __syncthreads();
    }
    if (threadIdx.x == 0) g_mx[blockIdx.x] = red[0];
}

// ---------------- K4: num/den = w @ [M*X | M], register-blocked over 24 hp ----------------
__global__ void __launch_bounds__(128) k_numden(const float* __restrict__ X,
                                                const float* __restrict__ M) {
    __shared__ float ws[NHP * 256];
    __shared__ float mxs[NHP];
    int tid = threadIdx.x;
    int b = blockIdx.y, lc = blockIdx.x;
    if (tid < NHP) mxs[tid] = g_mx[b * NHP + tid];
    __syncthreads();
    for (int idx = tid; idx < NHP * 256; idx += 128) {
        int hp = idx >> 8, l = idx & 255;
        ws[idx] = __expf(g_w[(b * NHP + hp) * cL + lc * 256 + l] - mxs[hp]);
    }
    __syncthreads();

    int c = tid;  // 0..127
    float an[NHP], ad[NHP];
#pragma unroll
    for (int hp = 0; hp < NHP; hp++) { an[hp] = 0.f; ad[hp] = 0.f; }

    const float* Xb = X + ((size_t)b * cL + (size_t)lc * 256) * cD + c;
    const float* Mb = M + ((size_t)b * cL + (size_t)lc * 256) * cD + c;
#pragma unroll 2
    for (int l = 0; l < 256; l++) {
        float xv = Xb[l * cD];
        float mv = Mb[l * cD];
        float mx = mv * xv;
#pragma unroll
        for (int hp = 0; hp < NHP; hp++) {
            float w = ws[hp * 256 + l];
            an[hp] = fmaf(w, mx, an[hp]);
            ad[hp] = fmaf(w, mv, ad[hp]);
        }
    }
#pragma unroll
    for (int hp = 0; hp < NHP; hp++) {
        atomicAdd(&g_num[(b * NHP + hp) * cD + c], an[hp]);
        atomicAdd(&g_den[(b * NHP + hp) * cD + c], ad[hp]);
    }
}

// ---------------- K5: coeffs[b][p][m] = ratio · W_o + b_o_eff ----------------
__global__ void __launch_bounds__(256) k_coeffs(const float* __restrict__ Wo) {
    __shared__ float rs[1024];
    int p = blockIdx.x, b = blockIdx.y, tid = threadIdx.x;
    for (int idx = tid; idx < 1024; idx += 256) {
        int h = idx >> 7, c = idx & 127;
        int hp = h * cP + p;
        rs[idx] = g_num[(b * NHP + hp) * cD + c] / g_den[(b * NHP + hp) * cD + c];
    }
    __syncthreads();
    int m = tid;
    float acc = g_boeff[m];
    for (int h = 0; h < cH; h++) {
        const float* Wor = &Wo[(h * 256) * cLAT + m];
#pragma unroll 4
        for (int c = 0; c < 128; c++)
            acc = fmaf(rs[h * 128 + c], Wor[c * cLAT], acc);
    }
    g_coeffs[(b * cP + p) * cLAT + m] = acc;
}

// ---------------- K6: g_i = c_i @ W1 (layer-1 GEMM collapsed per b) ----------------
__global__ void __launch_bounds__(512) k_g(const float* __restrict__ W1,
                                           const float* __restrict__ b1) {
    __shared__ float cs[3 * cLAT];
    int b = blockIdx.x, tid = threadIdx.x;
    for (int idx = tid; idx < 3 * cLAT; idx += 512) cs[idx] = g_coeffs[b * 3 * cLAT + idx];
    __syncthreads();
    int j = tid;
    float a0 = b1[j], a1 = 0.f, a2 = 0.f;
    for (int i = 0; i < cLAT; i++) {
        float w = W1[i * cHID + j];
        a0 = fmaf(cs[i], w, a0);
        a1 = fmaf(cs[cLAT + i], w, a1);
        a2 = fmaf(cs[2 * cLAT + i], w, a2);
    }
    g_gg[b * 3 * cHID + j] = a0;
    g_gg[b * 3 * cHID + cHID + j] = a1;
    g_gg[b * 3 * cHID + 2 * cHID + j] = a2;
}

// ---------------- K7: fused MLP  h1 -> h2 -> out  (dominant kernel) ----------------
// Block: 32 rows (one b), 256 threads. smem: h1[32][512], h2 chunk[32][128],
// W2 chunk[32][128], g[3][512], t[32].  Micro-tile 4r x 4c per thread.
#define K7_SMEM ((16384 + 4096 + 4096 + 1536 + 32) * 4)

__global__ void __launch_bounds__(256) k_mlp(const float* __restrict__ yts,
                                             const float* __restrict__ W2,
                                             const float* __restrict__ b2,
                                             const float* __restrict__ W3,
                                             const float* __restrict__ b3,
                                             float* __restrict__ out) {
    extern __shared__ float sm[];
    float* h1s = sm;                  // 32*512
    float* h2c = sm + 16384;          // 32*128
    float* w2s = sm + 16384 + 4096;   // 32*128
    float* gs  = sm + 16384 + 8192;   // 3*512
    float* ts  = gs + 1536;           // 32

    int tid = threadIdx.x;
    int b  = blockIdx.x >> 5;
    int r0 = (blockIdx.x & 31) << 5;

    for (int idx = tid; idx < 1536; idx += 256) gs[idx] = g_gg[b * 1536 + idx];
    if (tid < 32) ts[tid] = yts[b * cT + r0 + tid];
    __syncthreads();
    // h1 = relu(g0 + t*g1 + t^2*g2)   (layer-1 GEMM already folded)
    for (int idx = tid; idx < 32 * cHID; idx += 256) {
        int r = idx >> 9, j = idx & 511;
        float t = ts[r];
        float v = fmaf(t, fmaf(t, gs[1024 + j], gs[512 + j]), gs[j]);
        h1s[idx] = fmaxf(v, 0.f);
    }
    __syncthreads();

    int tk = tid & 31, tr = tid >> 5;

    float4 b3v = *(const float4*)(b3 + (tk << 2));
    float oa[4][4];
#pragma unroll
    for (int ri = 0; ri < 4; ri++) {
        oa[ri][0] = b3v.x; oa[ri][1] = b3v.y; oa[ri][2] = b3v.z; oa[ri][3] = b3v.w;
    }

    for (int kc = 0; kc < 4; kc++) {
        float4 b2v = *(const float4*)(b2 + kc * 128 + (tk << 2));
        float ac[4][4];
#pragma unroll
        for (int ri = 0; ri < 4; ri++) {
            ac[ri][0] = b2v.x; ac[ri][1] = b2v.y; ac[ri][2] = b2v.z; ac[ri][3] = b2v.w;
        }
        // layer 2: h2[32][128 chunk] = h1[32][512] @ W2[:, kc*128 : +128]
        for (int jc = 0; jc < 16; jc++) {
#pragma unroll
            for (int it = 0; it < 4; it++) {
                int lin = tid + (it << 8);
                int jj = lin >> 5, kk = lin & 31;
                *(float4*)(w2s + (jj << 7) + (kk << 2)) =
                    *(const float4*)(W2 + (size_t)(jc * 32 + jj) * cHID + kc * 128 + (kk << 2));
            }
            __syncthreads();
            int hbase = (tr << 2) * 512 + (jc << 5);
#pragma unroll
            for (int j = 0; j < 32; j++) {
                float a0 = h1s[hbase + j];
                float a1 = h1s[hbase + 512 + j];
                float a2 = h1s[hbase + 1024 + j];
                float a3 = h1s[hbase + 1536 + j];
                float4 bv = *(float4*)(w2s + (j << 7) + (tk << 2));
                ac[0][0] = fmaf(a0, bv.x, ac[0][0]); ac[0][1] = fmaf(a0, bv.y, ac[0][1]);
                ac[0][2] = fmaf(a0, bv.z, ac[0][2]); ac[0][3] = fmaf(a0, bv.w, ac[0][3]);
                ac[1][0] = fmaf(a1, bv.x, ac[1][0]); ac[1][1] = fmaf(a1, bv.y, ac[1][1]);
                ac[1][2] = fmaf(a1, bv.z, ac[1][2]); ac[1][3] = fmaf(a1, bv.w, ac[1][3]);
                ac[2][0] = fmaf(a2, bv.x, ac[2][0]); ac[2][1] = fmaf(a2, bv.y, ac[2][1]);
                ac[2][2] = fmaf(a2, bv.z, ac[2][2]); ac[2][3] = fmaf(a2, bv.w, ac[2][3]);
                ac[3][0] = fmaf(a3, bv.x, ac[3][0]); ac[3][1] = fmaf(a3, bv.y, ac[3][1]);
                ac[3][2] = fmaf(a3, bv.z, ac[3][2]); ac[3][3] = fmaf(a3, bv.w, ac[3][3]);
            }
            __syncthreads();
        }
        // relu -> h2 chunk in smem
#pragma unroll
        for (int ri = 0; ri < 4; ri++) {
            float4 hv;
            hv.x = fmaxf(ac[ri][0], 0.f); hv.y = fmaxf(ac[ri][1], 0.f);
            hv.z = fmaxf(ac[ri][2], 0.f); hv.w = fmaxf(ac[ri][3], 0.f);
            *(float4*)(h2c + (((tr << 2) + ri) << 7) + (tk << 2)) = hv;
        }
        __syncthreads();
        // layer 3 partial: out += h2chunk @ W3[kc*128 : +128, :]
        const float* W3c = W3 + kc * 128 * cD;
        int h2base = (tr << 2) << 7;
#pragma unroll 4
        for (int k = 0; k < 128; k++) {
            float4 wv = *(const float4*)(W3c + (k << 7) + (tk << 2));
            float h0 = h2c[h2base + k];
            float h1v = h2c[h2base + 128 + k];
            float h2v = h2c[h2base + 256 + k];
            float h3 = h2c[h2base + 384 + k];
            oa[0][0] = fmaf(h0, wv.x, oa[0][0]); oa[0][1] = fmaf(h0, wv.y, oa[0][1]);
            oa[0][2] = fmaf(h0, wv.z, oa[0][2]); oa[0][3] = fmaf(h0, wv.w, oa[0][3]);
            oa[1][0] = fmaf(h1v, wv.x, oa[1][0]); oa[1][1] = fmaf(h1v, wv.y, oa[1][1]);
            oa[1][2] = fmaf(h1v, wv.z, oa[1][2]); oa[1][3] = fmaf(h1v, wv.w, oa[1][3]);
            oa[2][0] = fmaf(h2v, wv.x, oa[2][0]); oa[2][1] = fmaf(h2v, wv.y, oa[2][1]);
            oa[2][2] = fmaf(h2v, wv.z, oa[2][2]); oa[2][3] = fmaf(h2v, wv.w, oa[2][3]);
            oa[3][0] = fmaf(h3, wv.x, oa[3][0]); oa[3][1] = fmaf(h3, wv.y, oa[3][1]);
            oa[3][2] = fmaf(h3, wv.z, oa[3][2]); oa[3][3] = fmaf(h3, wv.w, oa[3][3]);
        }
        __syncthreads();
    }

    size_t rowb = (size_t)b * cT + r0 + (tr << 2);
#pragma unroll
    for (int ri = 0; ri < 4; ri++) {
        float4 ov = make_float4(oa[ri][0], oa[ri][1], oa[ri][2], oa[ri][3]);
        *(float4*)(out + (rowb + ri) * cD + (tk << 2)) = ov;
    }
}

// ---------------- launch ----------------
extern "C" void kernel_launch(void* const* d_in, const int* in_sizes, int n_in,
                              void* d_out, int out_size) {
    const float* tsteps = (const float*)d_in[0];
    const float* X      = (const float*)d_in[1];
    const float* M      = (const float*)d_in[2];
    const float* yts    = (const float*)d_in[3];
    const float* wte    = (const float*)d_in[4];
    const float* bte    = (const float*)d_in[5];
    const float* query  = (const float*)d_in[6];
    const float* Wq     = (const float*)d_in[7];
    const float* bq     = (const float*)d_in[8];
    const float* Wk     = (const float*)d_in[9];
    const float* bk     = (const float*)d_in[10];
    const float* Wo     = (const float*)d_in[11];
    const float* bo     = (const float*)d_in[12];
    const float* W1     = (const float*)d_in[13];
    const float* b1     = (const float*)d_in[14];
    const float* W2     = (const float*)d_in[15];
    const float* b2     = (const float*)d_in[16];
    const float* W3     = (const float*)d_in[17];
    const float* b3     = (const float*)d_in[18];
    float* out = (float*)d_out;

    k_zero<<<(cB * NHP * cD + 255) / 256, 256>>>();
    k_q<<<cP, cE>>>(query, Wq, bq);
    k_kbar<<<1, cE>>>(wte, bte, Wk, bk);
    k_A<<<NHP, 96>>>(Wk);
    k_boeff<<<1, cLAT>>>(Wo, bo);
    k_scores<<<dim3(16, cB), 128>>>(tsteps, wte, bte);
    k_max<<<cB * NHP, 128>>>();
    k_numden<<<dim3(8, cB), 128>>>(X, M);
    k_coeffs<<<dim3(cP, cB), 256>>>(Wo);
    k_g<<<cB, cHID>>>(W1, b1);

    cudaFuncSetAttribute(k_mlp, cudaFuncAttributeMaxDynamicSharedMemorySize, K7_SMEM);
    k_mlp<<<(cB * cT) / 32, 256, K7_SMEM>>>(yts, W2, b2, W3, b3, out);
}

// round 4
// speedup vs baseline: 2.2879x; 2.2879x over previous
#include <cuda_runtime.h>
#include <math.h>
#include <stdint.h>

// Problem constants
#define cB   64
#define cL   2048
#define cT   1024
#define cD   128
#define cE   512
#define cH   8
#define cP   3
#define NHP  24      // H*P score functions
#define NF   66      // 64 sin features + t + const
#define cLAT 256
#define cHID 512
#define NROWS (cB * cT)   // 65536 MLP rows

// ---------------- device scratch (static, no allocation) ----------------
__device__ float g_q[cP * cE];
__device__ float g_kbar[cE];
__device__ float g_cbar[cE];
__device__ float g_A[NHP * NF];
__device__ float g_w[cB * NHP * cL];
__device__ float g_mx[cB * NHP];
__device__ float g_num[cB * NHP * cD];
__device__ float g_den[cB * NHP * cD];
__device__ float g_boeff[cLAT];
__device__ float g_coeffs[cB * cP * cLAT];
__device__ float g_gg[cB * 3 * cHID];
__device__ float g_h2[(size_t)NROWS * cHID];   // 134 MB intermediate h2

// ---------------- tf32 mma helpers ----------------
__device__ __forceinline__ uint32_t f2tf(float f) {
    uint32_t u;
    asm("cvt.rna.tf32.f32 %0, %1;" : "=r"(u) : "f"(f));
    return u;
}

__device__ __forceinline__ void mma8(float* d, const uint32_t* a, const uint32_t* b) {
    asm volatile(
        "mma.sync.aligned.m16n8k8.row.col.f32.tf32.tf32.f32 "
        "{%0,%1,%2,%3}, {%4,%5,%6,%7}, {%8,%9}, {%0,%1,%2,%3};"
        : "+f"(d[0]), "+f"(d[1]), "+f"(d[2]), "+f"(d[3])
        : "r"(a[0]), "r"(a[1]), "r"(a[2]), "r"(a[3]), "r"(b[0]), "r"(b[1]));
}

// ---------------- K0: zero accumulators ----------------
__global__ void k_zero() {
    int i = blockIdx.x * blockDim.x + threadIdx.x;
    if (i < cB * NHP * cD) { g_num[i] = 0.f; g_den[i] = 0.f; }
}

// ---------------- K1a: q[p][j] ----------------
__global__ void k_q(const float* __restrict__ query, const float* __restrict__ Wq,
                    const float* __restrict__ bq) {
    int p = blockIdx.x, j = threadIdx.x;
    __shared__ float qs[cE];
    for (int e = threadIdx.x; e < cE; e += blockDim.x) qs[e] = query[p * cE + e];
    __syncthreads();
    float acc = bq[j];
    for (int e = 0; e < cE; e++) acc = fmaf(qs[e], Wq[e * cE + j], acc);
    g_q[p * cE + j] = acc;
}

// ---------------- K1b: kbar / cbar ----------------
__global__ void k_kbar(const float* __restrict__ wte, const float* __restrict__ bte,
                       const float* __restrict__ Wk, const float* __restrict__ bk) {
    int j = threadIdx.x;
    float ak = 0.f, ac = bk[j];
    for (int e = 0; e < cE; e++) {
        if (e & 7) {
            float w = Wk[e * cE + j];
            ak = fmaf(wte[e], w, ak);
            ac = fmaf(bte[e], w, ac);
        }
    }
    g_kbar[j] = ak; g_cbar[j] = ac;
}

// ---------------- K1c: A[hp][i] ----------------
__global__ void k_A(const float* __restrict__ Wk) {
    int hp = blockIdx.x, i = threadIdx.x;
    if (i >= NF) return;
    int h = hp / cP, p = hp % cP;
    const float* qr = &g_q[p * cE + h * 64];
    float acc = 0.f;
    if (i < 64) {
        const float* wr = &Wk[(8 * i) * cE + h * 64];
        for (int j = 0; j < 64; j++) acc = fmaf(qr[j], wr[j], acc);
    } else if (i == 64) {
        const float* wr = &g_kbar[h * 64];
        for (int j = 0; j < 64; j++) acc = fmaf(qr[j], wr[j], acc);
    } else {
        const float* wr = &g_cbar[h * 64];
        for (int j = 0; j < 64; j++) acc = fmaf(qr[j], wr[j], acc);
    }
    g_A[hp * NF + i] = acc * 0.125f;
}

// ---------------- K1d: b_o_eff ----------------
__global__ void k_boeff(const float* __restrict__ Wo, const float* __restrict__ bo) {
    int m = threadIdx.x;
    float acc = bo[m];
    for (int h = 0; h < cH; h++)
        for (int c = 128; c < 256; c++)
            acc += Wo[(h * 256 + c) * cLAT + m];
    g_boeff[m] = acc;
}

// ---------------- K2: scores ----------------
__global__ void __launch_bounds__(128) k_scores(const float* __restrict__ tsteps,
                                                const float* __restrict__ wte,
                                                const float* __restrict__ bte) {
    __shared__ float As[NHP * NF];
    __shared__ float sw[64], sb[64];
    int tid = threadIdx.x;
    for (int idx = tid; idx < NHP * NF; idx += 128) As[idx] = g_A[idx];
    if (tid < 64) { sw[tid] = wte[8 * tid]; sb[tid] = bte[8 * tid]; }
    __syncthreads();

    int b = blockIdx.y;
    int l = blockIdx.x * 128 + tid;
    float t = tsteps[b * cL + l];
    float phi[64];
#pragma unroll
    for (int i = 0; i < 64; i++) phi[i] = __sinf(fmaf(t, sw[i], sb[i]));

    for (int hp = 0; hp < NHP; hp++) {
        const float* Ar = &As[hp * NF];
        float sc = fmaf(Ar[64], t, Ar[65]);
#pragma unroll
        for (int i = 0; i < 64; i++) sc = fmaf(Ar[i], phi[i], sc);
        g_w[(b * NHP + hp) * cL + l] = sc;
    }
}

// ---------------- K3: per (b,hp) max ----------------
__global__ void k_max() {
    __shared__ float red[128];
    int base = blockIdx.x * cL;
    float m = -1e30f;
    for (int l = threadIdx.x; l < cL; l += 128) m = fmaxf(m, g_w[base + l]);
    red[threadIdx.x] = m;
    __syncthreads();
    for (int s = 64; s > 0; s >>= 1) {
        if (threadIdx.x < s) red[threadIdx.x] = fmaxf(red[threadIdx.x], red[threadIdx.x + s]);
        __syncthreads();
    }
    if (threadIdx.x == 0) g_mx[blockIdx.x] = red[0];
}

// ---------------- K4: num/den ----------------
__global__ void __launch_bounds__(128) k_numden(const float* __restrict__ X,
                                                const float* __restrict__ M) {
    __shared__ float ws[NHP * 256];
    __shared__ float mxs[NHP];
    int tid = threadIdx.x;
    int b = blockIdx.y, lc = blockIdx.x;
    if (tid < NHP) mxs[tid] = g_mx[b * NHP + tid];
    __syncthreads();
    for (int idx = tid; idx < NHP * 256; idx += 128) {
        int hp = idx >> 8, l = idx & 255;
        ws[idx] = __expf(g_w[(b * NHP + hp) * cL + lc * 256 + l] - mxs[hp]);
    }
    __syncthreads();

    int c = tid;
    float an[NHP], ad[NHP];
#pragma unroll
    for (int hp = 0; hp < NHP; hp++) { an[hp] = 0.f; ad[hp] = 0.f; }

    const float* Xb = X + ((size_t)b * cL + (size_t)lc * 256) * cD + c;
    const float* Mb = M + ((size_t)b * cL + (size_t)lc * 256) * cD + c;
#pragma unroll 2
    for (int l = 0; l < 256; l++) {
        float xv = Xb[l * cD];
        float mv = Mb[l * cD];
        float mx = mv * xv;
#pragma unroll
        for (int hp = 0; hp < NHP; hp++) {
            float w = ws[hp * 256 + l];
            an[hp] = fmaf(w, mx, an[hp]);
            ad[hp] = fmaf(w, mv, ad[hp]);
        }
    }
#pragma unroll
    for (int hp = 0; hp < NHP; hp++) {
        atomicAdd(&g_num[(b * NHP + hp) * cD + c], an[hp]);
        atomicAdd(&g_den[(b * NHP + hp) * cD + c], ad[hp]);
    }
}

// ---------------- K5: coeffs ----------------
__global__ void __launch_bounds__(256) k_coeffs(const float* __restrict__ Wo) {
    __shared__ float rs[1024];
    int p = blockIdx.x, b = blockIdx.y, tid = threadIdx.x;
    for (int idx = tid; idx < 1024; idx += 256) {
        int h = idx >> 7, c = idx & 127;
        int hp = h * cP + p;
        rs[idx] = g_num[(b * NHP + hp) * cD + c] / g_den[(b * NHP + hp) * cD + c];
    }
    __syncthreads();
    int m = tid;
    float acc = g_boeff[m];
    for (int h = 0; h < cH; h++) {
        const float* Wor = &Wo[(h * 256) * cLAT + m];
#pragma unroll 4
        for (int c = 0; c < 128; c++)
            acc = fmaf(rs[h * 128 + c], Wor[c * cLAT], acc);
    }
    g_coeffs[(b * cP + p) * cLAT + m] = acc;
}

// ---------------- K6: g_i = c_i @ W1 ----------------
__global__ void __launch_bounds__(512) k_g(const float* __restrict__ W1,
                                           const float* __restrict__ b1) {
    __shared__ float cs[3 * cLAT];
    int b = blockIdx.x, tid = threadIdx.x;
    for (int idx = tid; idx < 3 * cLAT; idx += 512) cs[idx] = g_coeffs[b * 3 * cLAT + idx];
    __syncthreads();
    int j = tid;
    float a0 = b1[j], a1 = 0.f, a2 = 0.f;
    for (int i = 0; i < cLAT; i++) {
        float w = W1[i * cHID + j];
        a0 = fmaf(cs[i], w, a0);
        a1 = fmaf(cs[cLAT + i], w, a1);
        a2 = fmaf(cs[2 * cLAT + i], w, a2);
    }
    g_gg[b * 3 * cHID + j] = a0;
    g_gg[b * 3 * cHID + cHID + j] = a1;
    g_gg[b * 3 * cHID + 2 * cHID + j] = a2;
}

// ================= K7a: h2 = relu(h1 @ W2 + b2), tf32 tensor cores =========
// Block: 128 rows x 128 cols; 8 warps in 4(m) x 2(n); warp tile 32x64.
// A (h1) is generated in-kernel from g_gg poly; smem holds A/B in frag layout.
// smem floats: af 8192 | bf 8192 | ts 128 | gss 1536  -> 72192 bytes
#define G2_SMEM ((8192 + 8192 + 128 + 1536) * 4)

__global__ void __launch_bounds__(256) k_gemm2(const float* __restrict__ yts,
                                               const float* __restrict__ W2,
                                               const float* __restrict__ b2) {
    extern __shared__ float sm[];
    float* af  = sm;            // A frags: [mt(8)][ks(8)][lane(32)][4]
    float* bf  = sm + 8192;     // B frags: [nt(16)][ks(8)][lane(32)][2]
    float* ts  = sm + 16384;    // 128 t values
    float* gss = sm + 16512;    // g0|g1|g2, 512 each

    int tid = threadIdx.x, lane = tid & 31, wid = tid >> 5;
    int nb = blockIdx.x;        // 0..3  (n block of 128)
    int rb = blockIdx.y;        // 0..511 (row block of 128); b = rb>>3
    int b  = rb >> 3;
    int wm = wid >> 1, wn = wid & 1;

    if (tid < 128) ts[tid] = yts[b * cT + (rb & 7) * 128 + tid];
    for (int idx = tid; idx < 1536; idx += 256) gss[idx] = g_gg[b * 1536 + idx];

    float acc[2][8][4];
#pragma unroll
    for (int mi = 0; mi < 2; mi++)
#pragma unroll
        for (int ni = 0; ni < 8; ni++)
#pragma unroll
            for (int r = 0; r < 4; r++) acc[mi][ni][r] = 0.f;

    __syncthreads();

    for (int kc = 0; kc < 8; kc++) {
        // ---- generate A frags (h1 tile 128m x 64k) ----
#pragma unroll
        for (int it = 0; it < 8; it++) {
            int g = it * 256 + tid;
            int mt = g >> 8, ks = (g >> 5) & 7, ln = g & 31;
            int mb = mt * 16 + (ln >> 2);
            int kk = kc * 64 + ks * 8 + (ln & 3);
            float t0 = ts[mb], t1 = ts[mb + 8];
            float c0 = gss[kk],        c1 = gss[512 + kk],     c2 = gss[1024 + kk];
            float d0 = gss[kk + 4],    d1 = gss[512 + kk + 4], d2 = gss[1024 + kk + 4];
            float v00 = fmaxf(fmaf(t0, fmaf(t0, c2, c1), c0), 0.f);
            float v10 = fmaxf(fmaf(t1, fmaf(t1, c2, c1), c0), 0.f);
            float v01 = fmaxf(fmaf(t0, fmaf(t0, d2, d1), d0), 0.f);
            float v11 = fmaxf(fmaf(t1, fmaf(t1, d2, d1), d0), 0.f);
            uint4 u = make_uint4(f2tf(v00), f2tf(v10), f2tf(v01), f2tf(v11));
            ((uint4*)af)[g] = u;
        }
        // ---- load B frags (W2 chunk 64k x 128n) ----
#pragma unroll
        for (int it = 0; it < 16; it++) {
            int g = it * 256 + tid;
            int nt = g >> 8, ks = (g >> 5) & 7, ln = g & 31;
            int n = nt * 8 + (ln >> 2);
            int k = ks * 8 + (ln & 3);
            const float* Wp = W2 + (size_t)(kc * 64 + k) * cHID + nb * 128 + n;
            uint2 u = make_uint2(f2tf(Wp[0]), f2tf(Wp[4 * cHID]));
            ((uint2*)bf)[g] = u;
        }
        __syncthreads();

        // ---- mma mainloop ----
#pragma unroll
        for (int ks = 0; ks < 8; ks++) {
            uint4 a[2];
#pragma unroll
            for (int mi = 0; mi < 2; mi++)
                a[mi] = ((uint4*)af)[((wm * 2 + mi) * 8 + ks) * 32 + lane];
            uint2 bb[8];
#pragma unroll
            for (int ni = 0; ni < 8; ni++)
                bb[ni] = ((uint2*)bf)[((wn * 8 + ni) * 8 + ks) * 32 + lane];
#pragma unroll
            for (int mi = 0; mi < 2; mi++)
#pragma unroll
                for (int ni = 0; ni < 8; ni++)
                    mma8(acc[mi][ni], (const uint32_t*)&a[mi], (const uint32_t*)&bb[ni]);
        }
        __syncthreads();
    }

    // ---- epilogue: relu(acc + b2) -> g_h2 ----
    int row_base = rb * 128 + wm * 32;
#pragma unroll
    for (int mi = 0; mi < 2; mi++) {
        int r = row_base + mi * 16 + (lane >> 2);
#pragma unroll
        for (int ni = 0; ni < 8; ni++) {
            int n = nb * 128 + wn * 64 + ni * 8 + (lane & 3) * 2;
            float bx = b2[n], by = b2[n + 1];
            float2 v0 = make_float2(fmaxf(acc[mi][ni][0] + bx, 0.f),
                                    fmaxf(acc[mi][ni][1] + by, 0.f));
            float2 v1 = make_float2(fmaxf(acc[mi][ni][2] + bx, 0.f),
                                    fmaxf(acc[mi][ni][3] + by, 0.f));
            *(float2*)(g_h2 + (size_t)r * cHID + n) = v0;
            *(float2*)(g_h2 + (size_t)(r + 8) * cHID + n) = v1;
        }
    }
}

// ================= K7b: out = h2 @ W3 + b3, tf32 tensor cores ==============
// Block: 128 rows x 128 cols (full N); A loaded from g_h2.
#define G3_SMEM ((8192 + 8192) * 4)

__global__ void __launch_bounds__(256) k_gemm3(const float* __restrict__ W3,
                                               const float* __restrict__ b3,
                                               float* __restrict__ out) {
    extern __shared__ float sm[];
    float* af = sm;          // A frags
    float* bf = sm + 8192;   // B frags

    int tid = threadIdx.x, lane = tid & 31, wid = tid >> 5;
    int rb = blockIdx.y;     // 0..511
    int wm = wid >> 1, wn = wid & 1;

    float acc[2][8][4];
#pragma unroll
    for (int mi = 0; mi < 2; mi++)
#pragma unroll
        for (int ni = 0; ni < 8; ni++)
#pragma unroll
            for (int r = 0; r < 4; r++) acc[mi][ni][r] = 0.f;

    for (int kc = 0; kc < 8; kc++) {
        // ---- load A frags (h2 tile 128m x 64k from global) ----
#pragma unroll
        for (int it = 0; it < 8; it++) {
            int g = it * 256 + tid;
            int mt = g >> 8, ks = (g >> 5) & 7, ln = g & 31;
            int mb = mt * 16 + (ln >> 2);
            int kk = kc * 64 + ks * 8 + (ln & 3);
            const float* hp = g_h2 + (size_t)(rb * 128 + mb) * cHID + kk;
            uint4 u = make_uint4(f2tf(hp[0]), f2tf(hp[8 * cHID]),
                                 f2tf(hp[4]), f2tf(hp[8 * cHID + 4]));
            ((uint4*)af)[g] = u;
        }
        // ---- load B frags (W3 chunk 64k x 128n) ----
#pragma unroll
        for (int it = 0; it < 16; it++) {
            int g = it * 256 + tid;
            int nt = g >> 8, ks = (g >> 5) & 7, ln = g & 31;
            int n = nt * 8 + (ln >> 2);
            int k = ks * 8 + (ln & 3);
            const float* Wp = W3 + (size_t)(kc * 64 + k) * cD + n;
            uint2 u = make_uint2(f2tf(Wp[0]), f2tf(Wp[4 * cD]));
            ((uint2*)bf)[g] = u;
        }
        __syncthreads();

#pragma unroll
        for (int ks = 0; ks < 8; ks++) {
            uint4 a[2];
#pragma unroll
            for (int mi = 0; mi < 2; mi++)
                a[mi] = ((uint4*)af)[((wm * 2 + mi) * 8 + ks) * 32 + lane];
            uint2 bb[8];
#pragma unroll
            for (int ni = 0; ni < 8; ni++)
                bb[ni] = ((uint2*)bf)[((wn * 8 + ni) * 8 + ks) * 32 + lane];
#pragma unroll
            for (int mi = 0; mi < 2; mi++)
#pragma unroll
                for (int ni = 0; ni < 8; ni++)
                    mma8(acc[mi][ni], (const uint32_t*)&a[mi], (const uint32_t*)&bb[ni]);
        }
        __syncthreads();
    }

    // ---- epilogue: acc + b3 -> out ----
    int row_base = rb * 128 + wm * 32;
#pragma unroll
    for (int mi = 0; mi < 2; mi++) {
        int r = row_base + mi * 16 + (lane >> 2);
#pragma unroll
        for (int ni = 0; ni < 8; ni++) {
            int n = wn * 64 + ni * 8 + (lane & 3) * 2;
            float bx = b3[n], by = b3[n + 1];
            float2 v0 = make_float2(acc[mi][ni][0] + bx, acc[mi][ni][1] + by);
            float2 v1 = make_float2(acc[mi][ni][2] + bx, acc[mi][ni][3] + by);
            *(float2*)(out + (size_t)r * cD + n) = v0;
            *(float2*)(out + (size_t)(r + 8) * cD + n) = v1;
        }
    }
}

// ---------------- launch ----------------
extern "C" void kernel_launch(void* const* d_in, const int* in_sizes, int n_in,
                              void* d_out, int out_size) {
    const float* tsteps = (const float*)d_in[0];
    const float* X      = (const float*)d_in[1];
    const float* M      = (const float*)d_in[2];
    const float* yts    = (const float*)d_in[3];
    const float* wte    = (const float*)d_in[4];
    const float* bte    = (const float*)d_in[5];
    const float* query  = (const float*)d_in[6];
    const float* Wq     = (const float*)d_in[7];
    const float* bq     = (const float*)d_in[8];
    const float* Wk     = (const float*)d_in[9];
    const float* bk     = (const float*)d_in[10];
    const float* Wo     = (const float*)d_in[11];
    const float* bo     = (const float*)d_in[12];
    const float* W1     = (const float*)d_in[13];
    const float* b1     = (const float*)d_in[14];
    const float* W2     = (const float*)d_in[15];
    const float* b2     = (const float*)d_in[16];
    const float* W3     = (const float*)d_in[17];
    const float* b3     = (const float*)d_in[18];
    float* out = (float*)d_out;

    k_zero<<<(cB * NHP * cD + 255) / 256, 256>>>();
    k_q<<<cP, cE>>>(query, Wq, bq);
    k_kbar<<<1, cE>>>(wte, bte, Wk, bk);
    k_A<<<NHP, 96>>>(Wk);
    k_boeff<<<1, cLAT>>>(Wo, bo);
    k_scores<<<dim3(16, cB), 128>>>(tsteps, wte, bte);
    k_max<<<cB * NHP, 128>>>();
    k_numden<<<dim3(8, cB), 128>>>(X, M);
    k_coeffs<<<dim3(cP, cB), 256>>>(Wo);
    k_g<<<cB, cHID>>>(W1, b1);

    cudaFuncSetAttribute(k_gemm2, cudaFuncAttributeMaxDynamicSharedMemorySize, G2_SMEM);
    cudaFuncSetAttribute(k_gemm3, cudaFuncAttributeMaxDynamicSharedMemorySize, G3_SMEM);
    k_gemm2<<<dim3(4, 512), 256, G2_SMEM>>>(yts, W2, b2);
    k_gemm3<<<dim3(1, 512), 256, G3_SMEM>>>(W3, b3, out);
}